// round 1
// baseline (speedup 1.0000x reference)
#include <cuda_runtime.h>

#define B_   4
#define N_   4096
#define K_   512
#define NT   64
#define NPAIR (NT/2)
#define EPSF 1e-6f

typedef unsigned long long ull;

__device__ double g_acc[2];

__device__ __forceinline__ ull pack2(float lo, float hi) {
    ull r; asm("mov.b64 %0, {%1, %2};" : "=l"(r) : "f"(lo), "f"(hi)); return r;
}
__device__ __forceinline__ float2 unpack2(ull v) {
    float2 r; asm("mov.b64 {%0, %1}, %2;" : "=f"(r.x), "=f"(r.y) : "l"(v)); return r;
}
__device__ __forceinline__ ull fma2(ull a, ull b, ull c) {
    ull d; asm("fma.rn.f32x2 %0, %1, %2, %3;" : "=l"(d) : "l"(a), "l"(b), "l"(c)); return d;
}
__device__ __forceinline__ ull mul2(ull a, ull b) {
    ull d; asm("mul.rn.f32x2 %0, %1, %2;" : "=l"(d) : "l"(a), "l"(b)); return d;
}
__device__ __forceinline__ void lds2(unsigned addr, ull& x, ull& y) {
    asm("ld.shared.v2.b64 {%0, %1}, [%2];" : "=l"(x), "=l"(y) : "r"(addr));
}

// symmetric 3x3 inverse of (S + eps*I), S given as row-major 9 floats
__device__ __forceinline__ void inv3sym(const float* __restrict__ S,
                                        float& i00, float& i01, float& i02,
                                        float& i11, float& i12, float& i22) {
    float s00 = S[0] + EPSF, s01 = S[1], s02 = S[2];
    float s11 = S[4] + EPSF, s12 = S[5];
    float s22 = S[8] + EPSF;
    float c00 = s11 * s22 - s12 * s12;
    float c01 = s02 * s12 - s01 * s22;
    float c02 = s01 * s12 - s02 * s11;
    float c11 = s00 * s22 - s02 * s02;
    float c12 = s01 * s02 - s00 * s12;
    float c22 = s00 * s11 - s01 * s01;
    float det = s00 * c00 + s01 * c01 + s02 * c02;
    float id  = 1.0f / det;
    i00 = c00 * id; i01 = c01 * id; i02 = c02 * id;
    i11 = c11 * id; i12 = c12 * id; i22 = c22 * id;
}

__global__ void zero_acc_kernel() {
    g_acc[0] = 0.0;
    g_acc[1] = 0.0;
}

__global__ void __launch_bounds__(512, 1)
loss_kernel(const float* __restrict__ muC, const float* __restrict__ SC,
            const float* __restrict__ muP, const float* __restrict__ SP,
            const float* __restrict__ A,   const float* __restrict__ mask)
{
    __shared__ float sh[NPAIR * 40];   // per n-pair: 20 features x 2 slots
    __shared__ float redP[16], redC[16];

    const int b   = blockIdx.y;
    const int n0  = blockIdx.x * NT;
    const int tid = threadIdx.x;
    const int k   = tid;               // each thread owns one parent k

    // ---- parent features (registers, packed {v,v}) ----
    float i00, i01, i02, i11, i12, i22;
    inv3sym(SP + (size_t)(b * K_ + k) * 9, i00, i01, i02, i11, i12, i22);
    const float* mp = muP + (size_t)(b * K_ + k) * 3;
    float p0 = mp[0], p1 = mp[1], p2 = mp[2];
    float w0 = i00 * p0 + i01 * p1 + i02 * p2;
    float w1 = i01 * p0 + i11 * p1 + i12 * p2;
    float w2 = i02 * p0 + i12 * p1 + i22 * p2;
    float r  = p0 * w0 + p1 * w1 + p2 * w2;

    ull Pi00 = pack2(i00, i00), Pi11 = pack2(i11, i11), Pi22 = pack2(i22, i22);
    ull Pi01 = pack2(i01, i01), Pi02 = pack2(i02, i02), Pi12 = pack2(i12, i12);
    ull Pq0  = pack2(-2.f * w0, -2.f * w0);
    ull Pq1  = pack2(-2.f * w1, -2.f * w1);
    ull Pq2  = pack2(-2.f * w2, -2.f * w2);
    ull Pr   = pack2(r, r);
    ull Pp00 = pack2(p0 * p0, p0 * p0), Pp11 = pack2(p1 * p1, p1 * p1);
    ull Pp22 = pack2(p2 * p2, p2 * p2), Pp01 = pack2(p0 * p1, p0 * p1);
    ull Pp02 = pack2(p0 * p2, p0 * p2), Pp12 = pack2(p1 * p2, p1 * p2);
    ull Pm0  = pack2(-2.f * p0, -2.f * p0);
    ull Pm1  = pack2(-2.f * p1, -2.f * p1);
    ull Pm2  = pack2(-2.f * p2, -2.f * p2);

    // ---- child features -> shared (threads 0..NT-1) ----
    if (tid < NT) {
        int n = n0 + tid;
        float j00, j01, j02, j11, j12, j22;
        inv3sym(SC + (size_t)(b * N_ + n) * 9, j00, j01, j02, j11, j12, j22);
        const float* mc = muC + (size_t)(b * N_ + n) * 3;
        float c0 = mc[0], c1 = mc[1], c2 = mc[2];
        float u0 = j00 * c0 + j01 * c1 + j02 * c2;
        float u1 = j01 * c0 + j11 * c1 + j12 * c2;
        float u2 = j02 * c0 + j12 * c1 + j22 * c2;
        float tq = c0 * u0 + c1 * u1 + c2 * u2;
        float m  = mask[b * N_ + n];
        float* d = &sh[(tid >> 1) * 40 + (tid & 1)];
        d[0]  = c0 * c0;      d[2]  = c1 * c1;      d[4]  = c2 * c2;
        d[6]  = 2.f * c0 * c1; d[8]  = 2.f * c0 * c2; d[10] = 2.f * c1 * c2;
        d[12] = c0;           d[14] = c1;           d[16] = c2;
        d[18] = j00;          d[20] = j11;          d[22] = j22;
        d[24] = 2.f * j01;    d[26] = 2.f * j02;    d[28] = 2.f * j12;
        d[30] = u0;           d[32] = u1;           d[34] = u2;
        d[36] = tq;           d[38] = m;
    }
    __syncthreads();

    unsigned sbase = (unsigned)__cvta_generic_to_shared(sh);
    const float* Ap = A + ((size_t)b * N_ + n0) * K_ + k;

    // manual depth-4 prefetch of A pairs (keeps ~8 LDGs in flight per warp)
    float abuf[8];
#pragma unroll
    for (int i = 0; i < 4; i++) {
        abuf[2 * i]     = Ap[0];
        abuf[2 * i + 1] = Ap[K_];
        Ap += 2 * K_;
    }

    ull accP = 0ull, accC = 0ull;
#pragma unroll 4
    for (int p = 0; p < NPAIR; ++p) {
        float a0 = abuf[(p & 3) * 2];
        float a1 = abuf[(p & 3) * 2 + 1];
        if (p + 4 < NPAIR) {
            abuf[(p & 3) * 2]     = Ap[0];
            abuf[(p & 3) * 2 + 1] = Ap[K_];
            Ap += 2 * K_;
        }
        unsigned ad = sbase + p * 160;
        ull F0,F1,F2,F3,F4,F5,F6,F7,F8,F9,F10,F11,F12,F13,F14,F15,F16,F17,F18,F19;
        lds2(ad,       F0,  F1 );
        lds2(ad + 16,  F2,  F3 );
        lds2(ad + 32,  F4,  F5 );
        lds2(ad + 48,  F6,  F7 );
        lds2(ad + 64,  F8,  F9 );
        lds2(ad + 80,  F10, F11);
        lds2(ad + 96,  F12, F13);
        lds2(ad + 112, F14, F15);
        lds2(ad + 128, F16, F17);
        lds2(ad + 144, F18, F19);
        ull a2 = pack2(a0, a1);

        // maha_p = r - 2(Ip p).c + Ip : cc'
        ull mpv = fma2(F0, Pi00, Pr);
        mpv = fma2(F1, Pi11, mpv);
        mpv = fma2(F2, Pi22, mpv);
        mpv = fma2(F3, Pi01, mpv);
        mpv = fma2(F4, Pi02, mpv);
        mpv = fma2(F5, Pi12, mpv);
        mpv = fma2(F6, Pq0,  mpv);
        mpv = fma2(F7, Pq1,  mpv);
        mpv = fma2(F8, Pq2,  mpv);
        // maha_c = t - 2(Ic c).p + Ic' : pp
        ull mcv = fma2(F9,  Pp00, F18);
        mcv = fma2(F10, Pp11, mcv);
        mcv = fma2(F11, Pp22, mcv);
        mcv = fma2(F12, Pp01, mcv);
        mcv = fma2(F13, Pp02, mcv);
        mcv = fma2(F14, Pp12, mcv);
        mcv = fma2(F15, Pm0,  mcv);
        mcv = fma2(F16, Pm1,  mcv);
        mcv = fma2(F17, Pm2,  mcv);

        ull am = mul2(a2, F19);        // A * mask
        accP = fma2(am, mpv, accP);
        accC = fma2(am, mcv, accC);
    }

    // ---- reduction ----
    float2 vP = unpack2(accP), vC = unpack2(accC);
    float sp = vP.x + vP.y;
    float sc = vC.x + vC.y;
#pragma unroll
    for (int off = 16; off; off >>= 1) {
        sp += __shfl_down_sync(0xffffffffu, sp, off);
        sc += __shfl_down_sync(0xffffffffu, sc, off);
    }
    int wid = tid >> 5, lane = tid & 31;
    if (lane == 0) { redP[wid] = sp; redC[wid] = sc; }
    __syncthreads();
    if (tid < 16) {
        sp = redP[tid];
        sc = redC[tid];
#pragma unroll
        for (int off = 8; off; off >>= 1) {
            sp += __shfl_down_sync(0x0000ffffu, sp, off);
            sc += __shfl_down_sync(0x0000ffffu, sc, off);
        }
        if (tid == 0) {
            atomicAdd(&g_acc[0], (double)sp);
            atomicAdd(&g_acc[1], (double)sc);
        }
    }
}

__global__ void finalize_kernel(const float* __restrict__ mask, float* __restrict__ out) {
    __shared__ float red[256];
    float s = 0.f;
    for (int i = threadIdx.x; i < B_ * N_; i += 256) s += mask[i];
    red[threadIdx.x] = s;
    __syncthreads();
    for (int st = 128; st; st >>= 1) {
        if (threadIdx.x < st) red[threadIdx.x] += red[threadIdx.x + st];
        __syncthreads();
    }
    if (threadIdx.x == 0) {
        float ms = red[0];
        double denom = (ms > 1.f) ? (double)ms : 1.0;
        double p = g_acc[0], c = g_acc[1];
        out[0] = (float)((p + c) / denom);  // final_loss (W_p = W_c = 1)
        out[1] = (float)(p / denom);        // dist_p_m
        out[2] = (float)(c / denom);        // dist_c_m
    }
}

extern "C" void kernel_launch(void* const* d_in, const int* in_sizes, int n_in,
                              void* d_out, int out_size) {
    const float* muC  = (const float*)d_in[0];
    const float* SC   = (const float*)d_in[1];
    const float* muP  = (const float*)d_in[2];
    const float* SP   = (const float*)d_in[3];
    const float* A    = (const float*)d_in[4];
    const float* mask = (const float*)d_in[5];

    zero_acc_kernel<<<1, 1>>>();
    dim3 grid(N_ / NT, B_);
    loss_kernel<<<grid, 512>>>(muC, SC, muP, SP, A, mask);
    finalize_kernel<<<1, 256>>>(mask, (float*)d_out);
}

// round 2
// speedup vs baseline: 1.0770x; 1.0770x over previous
#include <cuda_runtime.h>

#define B_   4
#define N_   4096
#define K_   512
#define NT   64
#define NPAIR (NT/2)
#define GRID_X (N_/NT)          // 64
#define GRID_TOTAL (GRID_X*B_)  // 256
#define EPSF 1e-6f

typedef unsigned long long ull;

__device__ double   g_blkP[GRID_TOTAL];
__device__ double   g_blkC[GRID_TOTAL];
__device__ float    g_blkM[GRID_TOTAL];
__device__ unsigned g_cnt;   // zero-init; atomicInc wrap keeps it 0 after each full launch

__device__ __forceinline__ ull pack2(float lo, float hi) {
    ull r; asm("mov.b64 %0, {%1, %2};" : "=l"(r) : "f"(lo), "f"(hi)); return r;
}
__device__ __forceinline__ float2 unpack2(ull v) {
    float2 r; asm("mov.b64 {%0, %1}, %2;" : "=f"(r.x), "=f"(r.y) : "l"(v)); return r;
}
__device__ __forceinline__ ull fma2(ull a, ull b, ull c) {
    ull d; asm("fma.rn.f32x2 %0, %1, %2, %3;" : "=l"(d) : "l"(a), "l"(b), "l"(c)); return d;
}
__device__ __forceinline__ ull mul2(ull a, ull b) {
    ull d; asm("mul.rn.f32x2 %0, %1, %2;" : "=l"(d) : "l"(a), "l"(b)); return d;
}
__device__ __forceinline__ ull add2(ull a, ull b) {
    ull d; asm("add.rn.f32x2 %0, %1, %2;" : "=l"(d) : "l"(a), "l"(b)); return d;
}
__device__ __forceinline__ void lds2(unsigned addr, ull& x, ull& y) {
    asm("ld.shared.v2.b64 {%0, %1}, [%2];" : "=l"(x), "=l"(y) : "r"(addr));
}

// symmetric 3x3 inverse of (S + eps*I), S given as row-major 9 floats
__device__ __forceinline__ void inv3sym(const float* __restrict__ S,
                                        float& i00, float& i01, float& i02,
                                        float& i11, float& i12, float& i22) {
    float s00 = S[0] + EPSF, s01 = S[1], s02 = S[2];
    float s11 = S[4] + EPSF, s12 = S[5];
    float s22 = S[8] + EPSF;
    float c00 = s11 * s22 - s12 * s12;
    float c01 = s02 * s12 - s01 * s22;
    float c02 = s01 * s12 - s02 * s11;
    float c11 = s00 * s22 - s02 * s02;
    float c12 = s01 * s02 - s00 * s12;
    float c22 = s00 * s11 - s01 * s01;
    float det = s00 * c00 + s01 * c01 + s02 * c02;
    float id  = 1.0f / det;
    i00 = c00 * id; i01 = c01 * id; i02 = c02 * id;
    i11 = c11 * id; i12 = c12 * id; i22 = c22 * id;
}

__global__ void __launch_bounds__(512, 1)
loss_kernel(const float* __restrict__ muC, const float* __restrict__ SC,
            const float* __restrict__ muP, const float* __restrict__ SP,
            const float* __restrict__ A,   const float* __restrict__ mask,
            float* __restrict__ out)
{
    // per n-pair child features, interleaved {even,odd}:
    // c0,c1,c2, I00,I11,I22, 2*I01,2*I02,2*I12, m  -> 10 x 2 floats = 80B
    __shared__ float sh[NPAIR * 20];
    __shared__ float redP[16], redC[16];
    __shared__ float sMask;
    __shared__ int   sLast;

    const int b   = blockIdx.y;
    const int n0  = blockIdx.x * NT;
    const int tid = threadIdx.x;
    const int k   = tid;              // each thread owns one parent k

    // ---- parent features (9 packed regs) ----
    float i00, i01, i02, i11, i12, i22;
    inv3sym(SP + (size_t)(b * K_ + k) * 9, i00, i01, i02, i11, i12, i22);
    const float* mp = muP + (size_t)(b * K_ + k) * 3;
    float p0 = mp[0], p1 = mp[1], p2 = mp[2];
    ull Pn0  = pack2(-p0, -p0), Pn1 = pack2(-p1, -p1), Pn2 = pack2(-p2, -p2);
    ull PI00 = pack2(i00, i00), PI11 = pack2(i11, i11), PI22 = pack2(i22, i22);
    ull PI01 = pack2(2.f * i01, 2.f * i01);
    ull PI02 = pack2(2.f * i02, 2.f * i02);
    ull PI12 = pack2(2.f * i12, 2.f * i12);

    // ---- child features -> shared ----
    if (tid < NT) {
        int n = n0 + tid;
        float j00, j01, j02, j11, j12, j22;
        inv3sym(SC + (size_t)(b * N_ + n) * 9, j00, j01, j02, j11, j12, j22);
        const float* mc = muC + (size_t)(b * N_ + n) * 3;
        float* d = &sh[(tid >> 1) * 20 + (tid & 1)];
        d[0]  = mc[0];        d[2]  = mc[1];        d[4]  = mc[2];
        d[6]  = j00;          d[8]  = j11;          d[10] = j22;
        d[12] = 2.f * j01;    d[14] = 2.f * j02;    d[16] = 2.f * j12;
        d[18] = mask[b * N_ + n];
    }
    __syncthreads();

    // block mask partial (32 lanes, one pair each)
    if (tid < 32) {
        float m = sh[tid * 20 + 18] + sh[tid * 20 + 19];
#pragma unroll
        for (int off = 16; off; off >>= 1)
            m += __shfl_down_sync(0xffffffffu, m, off);
        if (tid == 0) sMask = m;
    }

    unsigned sbase = (unsigned)__cvta_generic_to_shared(sh);
    const float* Ap = A + ((size_t)b * N_ + n0) * K_ + k;

    // depth-4 prefetch of A pairs
    float abuf[8];
#pragma unroll
    for (int i = 0; i < 4; i++) {
        abuf[2 * i]     = Ap[0];
        abuf[2 * i + 1] = Ap[K_];
        Ap += 2 * K_;
    }

    ull accP = 0ull, accC = 0ull;
#pragma unroll 4
    for (int p = 0; p < NPAIR; ++p) {
        float a0 = abuf[(p & 3) * 2];
        float a1 = abuf[(p & 3) * 2 + 1];
        if (p + 4 < NPAIR) {
            abuf[(p & 3) * 2]     = Ap[0];
            abuf[(p & 3) * 2 + 1] = Ap[K_];
            Ap += 2 * K_;
        }
        unsigned ad = sbase + p * 80;
        ull Fc0, Fc1, Fc2, FI00, FI11, FI22, FI01, FI02, FI12, Fm;
        lds2(ad,      Fc0,  Fc1 );
        lds2(ad + 16, Fc2,  FI00);
        lds2(ad + 32, FI11, FI22);
        lds2(ad + 48, FI01, FI02);
        lds2(ad + 64, FI12, Fm  );

        ull d0 = add2(Fc0, Pn0);
        ull d1 = add2(Fc1, Pn1);
        ull d2 = add2(Fc2, Pn2);
        ull dd00 = mul2(d0, d0);
        ull dd11 = mul2(d1, d1);
        ull dd22 = mul2(d2, d2);
        ull dd01 = mul2(d0, d1);
        ull dd02 = mul2(d0, d2);
        ull dd12 = mul2(d1, d2);

        ull mpv = mul2(dd00, PI00);
        mpv = fma2(dd11, PI11, mpv);
        mpv = fma2(dd22, PI22, mpv);
        mpv = fma2(dd01, PI01, mpv);
        mpv = fma2(dd02, PI02, mpv);
        mpv = fma2(dd12, PI12, mpv);

        ull mcv = mul2(dd00, FI00);
        mcv = fma2(dd11, FI11, mcv);
        mcv = fma2(dd22, FI22, mcv);
        mcv = fma2(dd01, FI01, mcv);
        mcv = fma2(dd02, FI02, mcv);
        mcv = fma2(dd12, FI12, mcv);

        ull am = mul2(pack2(a0, a1), Fm);   // A * mask
        accP = fma2(am, mpv, accP);
        accC = fma2(am, mcv, accC);
    }

    // ---- in-block reduction ----
    float2 vP = unpack2(accP), vC = unpack2(accC);
    float sp = vP.x + vP.y;
    float sc = vC.x + vC.y;
#pragma unroll
    for (int off = 16; off; off >>= 1) {
        sp += __shfl_down_sync(0xffffffffu, sp, off);
        sc += __shfl_down_sync(0xffffffffu, sc, off);
    }
    int wid = tid >> 5, lane = tid & 31;
    if (lane == 0) { redP[wid] = sp; redC[wid] = sc; }
    __syncthreads();

    const int bid = blockIdx.y * gridDim.x + blockIdx.x;
    if (tid == 0) {
        float tp = 0.f, tc = 0.f;
#pragma unroll
        for (int i = 0; i < 16; i++) { tp += redP[i]; tc += redC[i]; }
        g_blkP[bid] = (double)tp;
        g_blkC[bid] = (double)tc;
        g_blkM[bid] = sMask;
        __threadfence();
        unsigned t = atomicInc(&g_cnt, GRID_TOTAL - 1);
        sLast = (t == GRID_TOTAL - 1);
    }
    __syncthreads();

    // ---- last block: final reduction + output ----
    if (sLast) {
        __threadfence();
        __shared__ double fP[16], fC[16];
        __shared__ float  fM[16];
        double p = 0.0, c = 0.0;
        float  m = 0.f;
        if (tid < GRID_TOTAL) {        // 256 threads, one slot each
            p = g_blkP[tid];
            c = g_blkC[tid];
            m = g_blkM[tid];
        }
#pragma unroll
        for (int off = 16; off; off >>= 1) {
            p += __shfl_down_sync(0xffffffffu, p, off);
            c += __shfl_down_sync(0xffffffffu, c, off);
            m += __shfl_down_sync(0xffffffffu, m, off);
        }
        if (lane == 0 && wid < 16) { fP[wid] = p; fC[wid] = c; fM[wid] = m; }
        __syncthreads();
        if (tid == 0) {
            double tp = 0.0, tc = 0.0;
            float  tm = 0.f;
#pragma unroll
            for (int i = 0; i < 8; i++) { tp += fP[i]; tc += fC[i]; tm += fM[i]; }
            double denom = (tm > 1.f) ? (double)tm : 1.0;
            out[0] = (float)((tp + tc) / denom);  // final_loss
            out[1] = (float)(tp / denom);          // dist_p_m
            out[2] = (float)(tc / denom);          // dist_c_m
        }
    }
}

extern "C" void kernel_launch(void* const* d_in, const int* in_sizes, int n_in,
                              void* d_out, int out_size) {
    const float* muC  = (const float*)d_in[0];
    const float* SC   = (const float*)d_in[1];
    const float* muP  = (const float*)d_in[2];
    const float* SP   = (const float*)d_in[3];
    const float* A    = (const float*)d_in[4];
    const float* mask = (const float*)d_in[5];

    dim3 grid(GRID_X, B_);
    loss_kernel<<<grid, 512>>>(muC, SC, muP, SP, A, mask, (float*)d_out);
}

// round 3
// speedup vs baseline: 1.1972x; 1.1116x over previous
#include <cuda_runtime.h>

#define B_   4
#define N_   4096
#define K_   512
#define NT   128
#define NPAIR (NT/2)            // 64
#define GRID_X (N_/NT)          // 32
#define GRID_TOTAL (GRID_X*B_)  // 128
#define DEPTH 8                 // A prefetch depth (pairs)
#define EPSF 1e-6f

typedef unsigned long long ull;

__device__ double   g_blkP[GRID_TOTAL];
__device__ double   g_blkC[GRID_TOTAL];
__device__ float    g_blkM[GRID_TOTAL];
__device__ unsigned g_cnt;   // zero-init; atomicInc wrap keeps it 0 after each full launch

__device__ __forceinline__ ull pack2(float lo, float hi) {
    ull r; asm("mov.b64 %0, {%1, %2};" : "=l"(r) : "f"(lo), "f"(hi)); return r;
}
__device__ __forceinline__ float2 unpack2(ull v) {
    float2 r; asm("mov.b64 {%0, %1}, %2;" : "=f"(r.x), "=f"(r.y) : "l"(v)); return r;
}
__device__ __forceinline__ ull fma2(ull a, ull b, ull c) {
    ull d; asm("fma.rn.f32x2 %0, %1, %2, %3;" : "=l"(d) : "l"(a), "l"(b), "l"(c)); return d;
}
__device__ __forceinline__ ull mul2(ull a, ull b) {
    ull d; asm("mul.rn.f32x2 %0, %1, %2;" : "=l"(d) : "l"(a), "l"(b)); return d;
}
__device__ __forceinline__ ull add2(ull a, ull b) {
    ull d; asm("add.rn.f32x2 %0, %1, %2;" : "=l"(d) : "l"(a), "l"(b)); return d;
}
__device__ __forceinline__ void lds2(unsigned addr, ull& x, ull& y) {
    asm("ld.shared.v2.b64 {%0, %1}, [%2];" : "=l"(x), "=l"(y) : "r"(addr));
}

// symmetric 3x3 inverse of (S + eps*I), S given as row-major 9 floats
__device__ __forceinline__ void inv3sym(const float* __restrict__ S,
                                        float& i00, float& i01, float& i02,
                                        float& i11, float& i12, float& i22) {
    float s00 = S[0] + EPSF, s01 = S[1], s02 = S[2];
    float s11 = S[4] + EPSF, s12 = S[5];
    float s22 = S[8] + EPSF;
    float c00 = s11 * s22 - s12 * s12;
    float c01 = s02 * s12 - s01 * s22;
    float c02 = s01 * s12 - s02 * s11;
    float c11 = s00 * s22 - s02 * s02;
    float c12 = s01 * s02 - s00 * s12;
    float c22 = s00 * s11 - s01 * s01;
    float det = s00 * c00 + s01 * c01 + s02 * c02;
    float id  = 1.0f / det;
    i00 = c00 * id; i01 = c01 * id; i02 = c02 * id;
    i11 = c11 * id; i12 = c12 * id; i22 = c22 * id;
}

__global__ void __launch_bounds__(512, 1)
loss_kernel(const float* __restrict__ muC, const float* __restrict__ SC,
            const float* __restrict__ muP, const float* __restrict__ SP,
            const float* __restrict__ A,   const float* __restrict__ mask,
            float* __restrict__ out)
{
    // per n-pair child features, interleaved {even,odd}:
    // c0,c1,c2, I00,I11,I22, 2*I01,2*I02,2*I12, m  -> 10 x 2 floats = 80B
    __shared__ float sh[NPAIR * 20];
    __shared__ float redP[16], redC[16];
    __shared__ float sMask;
    __shared__ int   sLast;

    const int b   = blockIdx.y;
    const int n0  = blockIdx.x * NT;
    const int tid = threadIdx.x;
    const int k   = tid;              // each thread owns one parent k

    // ---- parent features (9 packed regs) ----
    float i00, i01, i02, i11, i12, i22;
    inv3sym(SP + (size_t)(b * K_ + k) * 9, i00, i01, i02, i11, i12, i22);
    const float* mp = muP + (size_t)(b * K_ + k) * 3;
    float p0 = mp[0], p1 = mp[1], p2 = mp[2];
    ull Pn0  = pack2(-p0, -p0), Pn1 = pack2(-p1, -p1), Pn2 = pack2(-p2, -p2);
    ull PI00 = pack2(i00, i00), PI11 = pack2(i11, i11), PI22 = pack2(i22, i22);
    ull PI01 = pack2(2.f * i01, 2.f * i01);
    ull PI02 = pack2(2.f * i02, 2.f * i02);
    ull PI12 = pack2(2.f * i12, 2.f * i12);

    // ---- child features -> shared (threads 0..NT-1, one child each) ----
    if (tid < NT) {
        int n = n0 + tid;
        float j00, j01, j02, j11, j12, j22;
        inv3sym(SC + (size_t)(b * N_ + n) * 9, j00, j01, j02, j11, j12, j22);
        const float* mc = muC + (size_t)(b * N_ + n) * 3;
        float* d = &sh[(tid >> 1) * 20 + (tid & 1)];
        d[0]  = mc[0];        d[2]  = mc[1];        d[4]  = mc[2];
        d[6]  = j00;          d[8]  = j11;          d[10] = j22;
        d[12] = 2.f * j01;    d[14] = 2.f * j02;    d[16] = 2.f * j12;
        d[18] = mask[b * N_ + n];
    }
    __syncthreads();

    // block mask partial: warp 0, each lane sums 2 pairs (NPAIR=64)
    if (tid < 32) {
        float m = sh[tid * 20 + 18] + sh[tid * 20 + 19]
                + sh[(tid + 32) * 20 + 18] + sh[(tid + 32) * 20 + 19];
#pragma unroll
        for (int off = 16; off; off >>= 1)
            m += __shfl_down_sync(0xffffffffu, m, off);
        if (tid == 0) sMask = m;
    }

    unsigned sbase = (unsigned)__cvta_generic_to_shared(sh);
    const float* Ap = A + ((size_t)b * N_ + n0) * K_ + k;

    // depth-8 prefetch of A pairs (16 outstanding LDGs/thread)
    float abuf[2 * DEPTH];
#pragma unroll
    for (int i = 0; i < DEPTH; i++) {
        abuf[2 * i]     = Ap[0];
        abuf[2 * i + 1] = Ap[K_];
        Ap += 2 * K_;
    }

    ull accP = 0ull, accC = 0ull;
#pragma unroll 8
    for (int p = 0; p < NPAIR; ++p) {
        float a0 = abuf[(p & (DEPTH - 1)) * 2];
        float a1 = abuf[(p & (DEPTH - 1)) * 2 + 1];
        if (p + DEPTH < NPAIR) {
            abuf[(p & (DEPTH - 1)) * 2]     = Ap[0];
            abuf[(p & (DEPTH - 1)) * 2 + 1] = Ap[K_];
            Ap += 2 * K_;
        }
        unsigned ad = sbase + p * 80;
        ull Fc0, Fc1, Fc2, FI00, FI11, FI22, FI01, FI02, FI12, Fm;
        lds2(ad,      Fc0,  Fc1 );
        lds2(ad + 16, Fc2,  FI00);
        lds2(ad + 32, FI11, FI22);
        lds2(ad + 48, FI01, FI02);
        lds2(ad + 64, FI12, Fm  );

        ull d0 = add2(Fc0, Pn0);
        ull d1 = add2(Fc1, Pn1);
        ull d2 = add2(Fc2, Pn2);
        ull dd00 = mul2(d0, d0);
        ull dd11 = mul2(d1, d1);
        ull dd22 = mul2(d2, d2);
        ull dd01 = mul2(d0, d1);
        ull dd02 = mul2(d0, d2);
        ull dd12 = mul2(d1, d2);

        ull mpv = mul2(dd00, PI00);
        mpv = fma2(dd11, PI11, mpv);
        mpv = fma2(dd22, PI22, mpv);
        mpv = fma2(dd01, PI01, mpv);
        mpv = fma2(dd02, PI02, mpv);
        mpv = fma2(dd12, PI12, mpv);

        ull mcv = mul2(dd00, FI00);
        mcv = fma2(dd11, FI11, mcv);
        mcv = fma2(dd22, FI22, mcv);
        mcv = fma2(dd01, FI01, mcv);
        mcv = fma2(dd02, FI02, mcv);
        mcv = fma2(dd12, FI12, mcv);

        ull am = mul2(pack2(a0, a1), Fm);   // A * mask
        accP = fma2(am, mpv, accP);
        accC = fma2(am, mcv, accC);
    }

    // ---- in-block reduction ----
    float2 vP = unpack2(accP), vC = unpack2(accC);
    float sp = vP.x + vP.y;
    float sc = vC.x + vC.y;
#pragma unroll
    for (int off = 16; off; off >>= 1) {
        sp += __shfl_down_sync(0xffffffffu, sp, off);
        sc += __shfl_down_sync(0xffffffffu, sc, off);
    }
    int wid = tid >> 5, lane = tid & 31;
    if (lane == 0) { redP[wid] = sp; redC[wid] = sc; }
    __syncthreads();

    const int bid = blockIdx.y * gridDim.x + blockIdx.x;
    if (tid == 0) {
        float tp = 0.f, tc = 0.f;
#pragma unroll
        for (int i = 0; i < 16; i++) { tp += redP[i]; tc += redC[i]; }
        g_blkP[bid] = (double)tp;
        g_blkC[bid] = (double)tc;
        g_blkM[bid] = sMask;
        __threadfence();
        unsigned t = atomicInc(&g_cnt, GRID_TOTAL - 1);
        sLast = (t == GRID_TOTAL - 1);
    }
    __syncthreads();

    // ---- last block: final reduction + output ----
    if (sLast) {
        __threadfence();
        __shared__ double fP[16], fC[16];
        __shared__ float  fM[16];
        double p = 0.0, c = 0.0;
        float  m = 0.f;
        if (tid < GRID_TOTAL) {        // 128 slots
            p = g_blkP[tid];
            c = g_blkC[tid];
            m = g_blkM[tid];
        }
#pragma unroll
        for (int off = 16; off; off >>= 1) {
            p += __shfl_down_sync(0xffffffffu, p, off);
            c += __shfl_down_sync(0xffffffffu, c, off);
            m += __shfl_down_sync(0xffffffffu, m, off);
        }
        if (lane == 0 && wid < 16) { fP[wid] = p; fC[wid] = c; fM[wid] = m; }
        __syncthreads();
        if (tid == 0) {
            double tp = 0.0, tc = 0.0;
            float  tm = 0.f;
#pragma unroll
            for (int i = 0; i < 4; i++) { tp += fP[i]; tc += fC[i]; tm += fM[i]; }
            double denom = (tm > 1.f) ? (double)tm : 1.0;
            out[0] = (float)((tp + tc) / denom);  // final_loss
            out[1] = (float)(tp / denom);          // dist_p_m
            out[2] = (float)(tc / denom);          // dist_c_m
        }
    }
}

extern "C" void kernel_launch(void* const* d_in, const int* in_sizes, int n_in,
                              void* d_out, int out_size) {
    const float* muC  = (const float*)d_in[0];
    const float* SC   = (const float*)d_in[1];
    const float* muP  = (const float*)d_in[2];
    const float* SP   = (const float*)d_in[3];
    const float* A    = (const float*)d_in[4];
    const float* mask = (const float*)d_in[5];

    dim3 grid(GRID_X, B_);
    loss_kernel<<<grid, 512>>>(muC, SC, muP, SP, A, mask, (float*)d_out);
}

// round 4
// speedup vs baseline: 1.3249x; 1.1066x over previous
#include <cuda_runtime.h>

#define B_   4
#define N_   4096
#define K_   512
#define NT   64
#define NPAIR (NT/2)            // 32
#define GRID_X (N_/NT)          // 64
#define GRID_TOTAL (GRID_X*B_)  // 256
#define NTHR 256                // threads per CTA; each owns 2 parents
#define DEPTH 4                 // A prefetch depth (iters), 4 LDG/iter in flight
#define EPSF 1e-6f

typedef unsigned long long ull;

__device__ double   g_blkP[GRID_TOTAL];
__device__ double   g_blkC[GRID_TOTAL];
__device__ float    g_blkM[GRID_TOTAL];
__device__ unsigned g_cnt;   // zero-init; atomicInc wrap keeps it 0 after each launch

__device__ __forceinline__ ull pack2(float lo, float hi) {
    ull r; asm("mov.b64 %0, {%1, %2};" : "=l"(r) : "f"(lo), "f"(hi)); return r;
}
__device__ __forceinline__ float2 unpack2(ull v) {
    float2 r; asm("mov.b64 {%0, %1}, %2;" : "=f"(r.x), "=f"(r.y) : "l"(v)); return r;
}
__device__ __forceinline__ ull fma2(ull a, ull b, ull c) {
    ull d; asm("fma.rn.f32x2 %0, %1, %2, %3;" : "=l"(d) : "l"(a), "l"(b), "l"(c)); return d;
}
__device__ __forceinline__ ull mul2(ull a, ull b) {
    ull d; asm("mul.rn.f32x2 %0, %1, %2;" : "=l"(d) : "l"(a), "l"(b)); return d;
}
__device__ __forceinline__ ull add2(ull a, ull b) {
    ull d; asm("add.rn.f32x2 %0, %1, %2;" : "=l"(d) : "l"(a), "l"(b)); return d;
}
__device__ __forceinline__ void lds2(unsigned addr, ull& x, ull& y) {
    asm("ld.shared.v2.b64 {%0, %1}, [%2];" : "=l"(x), "=l"(y) : "r"(addr));
}

// symmetric 3x3 inverse of (S + eps*I)
__device__ __forceinline__ void inv3sym(const float* __restrict__ S,
                                        float& i00, float& i01, float& i02,
                                        float& i11, float& i12, float& i22) {
    float s00 = S[0] + EPSF, s01 = S[1], s02 = S[2];
    float s11 = S[4] + EPSF, s12 = S[5];
    float s22 = S[8] + EPSF;
    float c00 = s11 * s22 - s12 * s12;
    float c01 = s02 * s12 - s01 * s22;
    float c02 = s01 * s12 - s02 * s11;
    float c11 = s00 * s22 - s02 * s02;
    float c12 = s01 * s02 - s00 * s12;
    float c22 = s00 * s11 - s01 * s01;
    float det = s00 * c00 + s01 * c01 + s02 * c02;
    float id  = 1.0f / det;
    i00 = c00 * id; i01 = c01 * id; i02 = c02 * id;
    i11 = c11 * id; i12 = c12 * id; i22 = c22 * id;
}

struct PFeat { ull Pn0, Pn1, Pn2, PI00, PI11, PI22, PI01, PI02, PI12; };

__device__ __forceinline__ PFeat load_parent(const float* SP, const float* muP,
                                             int b, int k) {
    float i00, i01, i02, i11, i12, i22;
    inv3sym(SP + (size_t)(b * K_ + k) * 9, i00, i01, i02, i11, i12, i22);
    const float* mp = muP + (size_t)(b * K_ + k) * 3;
    float p0 = mp[0], p1 = mp[1], p2 = mp[2];
    PFeat f;
    f.Pn0  = pack2(-p0, -p0); f.Pn1 = pack2(-p1, -p1); f.Pn2 = pack2(-p2, -p2);
    f.PI00 = pack2(i00, i00); f.PI11 = pack2(i11, i11); f.PI22 = pack2(i22, i22);
    f.PI01 = pack2(2.f * i01, 2.f * i01);
    f.PI02 = pack2(2.f * i02, 2.f * i02);
    f.PI12 = pack2(2.f * i12, 2.f * i12);
    return f;
}

// one (n-pair x one-parent) update
__device__ __forceinline__ void body_k(const PFeat& P,
                                       ull Fc0, ull Fc1, ull Fc2,
                                       ull FI00, ull FI11, ull FI22,
                                       ull FI01, ull FI02, ull FI12,
                                       ull am, ull& accP, ull& accC) {
    ull d0 = add2(Fc0, P.Pn0);
    ull d1 = add2(Fc1, P.Pn1);
    ull d2 = add2(Fc2, P.Pn2);
    ull dd00 = mul2(d0, d0);
    ull dd11 = mul2(d1, d1);
    ull dd22 = mul2(d2, d2);
    ull dd01 = mul2(d0, d1);
    ull dd02 = mul2(d0, d2);
    ull dd12 = mul2(d1, d2);

    ull mpv = mul2(dd00, P.PI00);
    mpv = fma2(dd11, P.PI11, mpv);
    mpv = fma2(dd22, P.PI22, mpv);
    mpv = fma2(dd01, P.PI01, mpv);
    mpv = fma2(dd02, P.PI02, mpv);
    mpv = fma2(dd12, P.PI12, mpv);

    ull mcv = mul2(dd00, FI00);
    mcv = fma2(dd11, FI11, mcv);
    mcv = fma2(dd22, FI22, mcv);
    mcv = fma2(dd01, FI01, mcv);
    mcv = fma2(dd02, FI02, mcv);
    mcv = fma2(dd12, FI12, mcv);

    accP = fma2(am, mpv, accP);
    accC = fma2(am, mcv, accC);
}

__global__ void __launch_bounds__(NTHR, 2)
loss_kernel(const float* __restrict__ muC, const float* __restrict__ SC,
            const float* __restrict__ muP, const float* __restrict__ SP,
            const float* __restrict__ A,   const float* __restrict__ mask,
            float* __restrict__ out)
{
    // per n-pair child features, interleaved {even,odd}:
    // c0,c1,c2, I00,I11,I22, 2*I01,2*I02,2*I12, m  -> 10 x 2 floats = 80B
    __shared__ float sh[NPAIR * 20];
    __shared__ float redP[8], redC[8];
    __shared__ float sMask;
    __shared__ int   sLast;

    const int b   = blockIdx.y;
    const int n0  = blockIdx.x * NT;
    const int tid = threadIdx.x;
    const int k1  = tid;              // parents k1 and k1+256
    const int k2  = tid + NTHR;

    PFeat P1 = load_parent(SP, muP, b, k1);
    PFeat P2 = load_parent(SP, muP, b, k2);

    // ---- child features -> shared (threads 0..NT-1, one child each) ----
    if (tid < NT) {
        int n = n0 + tid;
        float j00, j01, j02, j11, j12, j22;
        inv3sym(SC + (size_t)(b * N_ + n) * 9, j00, j01, j02, j11, j12, j22);
        const float* mc = muC + (size_t)(b * N_ + n) * 3;
        float* d = &sh[(tid >> 1) * 20 + (tid & 1)];
        d[0]  = mc[0];        d[2]  = mc[1];        d[4]  = mc[2];
        d[6]  = j00;          d[8]  = j11;          d[10] = j22;
        d[12] = 2.f * j01;    d[14] = 2.f * j02;    d[16] = 2.f * j12;
        d[18] = mask[b * N_ + n];
    }
    __syncthreads();

    // block mask partial: warp 0, one n-pair per lane (NPAIR=32)
    if (tid < 32) {
        float m = sh[tid * 20 + 18] + sh[tid * 20 + 19];
#pragma unroll
        for (int off = 16; off; off >>= 1)
            m += __shfl_down_sync(0xffffffffu, m, off);
        if (tid == 0) sMask = m;
    }

    unsigned sbase = (unsigned)__cvta_generic_to_shared(sh);
    const float* Ap = A + ((size_t)b * N_ + n0) * K_ + k1;

    // depth-4 prefetch of A (4 loads per iter: {n,n+1} x {k1,k2})
    float abuf[4 * DEPTH];
#pragma unroll
    for (int i = 0; i < DEPTH; i++) {
        abuf[4 * i]     = Ap[0];
        abuf[4 * i + 1] = Ap[K_];
        abuf[4 * i + 2] = Ap[NTHR];
        abuf[4 * i + 3] = Ap[NTHR + K_];
        Ap += 2 * K_;
    }

    ull accP = 0ull, accC = 0ull;

#pragma unroll 4
    for (int p = 0; p < NPAIR; ++p) {
        int s = (p & (DEPTH - 1)) * 4;
        float a0 = abuf[s], a1 = abuf[s + 1], a2 = abuf[s + 2], a3 = abuf[s + 3];
        if (p < NPAIR - DEPTH) {
            abuf[s]     = Ap[0];
            abuf[s + 1] = Ap[K_];
            abuf[s + 2] = Ap[NTHR];
            abuf[s + 3] = Ap[NTHR + K_];
            Ap += 2 * K_;
        }
        unsigned ad = sbase + p * 80;
        ull Fc0, Fc1, Fc2, FI00, FI11, FI22, FI01, FI02, FI12, Fm;
        lds2(ad,      Fc0,  Fc1 );
        lds2(ad + 16, Fc2,  FI00);
        lds2(ad + 32, FI11, FI22);
        lds2(ad + 48, FI01, FI02);
        lds2(ad + 64, FI12, Fm  );

        ull am1 = mul2(pack2(a0, a1), Fm);
        ull am2 = mul2(pack2(a2, a3), Fm);
        body_k(P1, Fc0, Fc1, Fc2, FI00, FI11, FI22, FI01, FI02, FI12, am1, accP, accC);
        body_k(P2, Fc0, Fc1, Fc2, FI00, FI11, FI22, FI01, FI02, FI12, am2, accP, accC);
    }

    // ---- in-block reduction ----
    float2 vP = unpack2(accP), vC = unpack2(accC);
    float sp = vP.x + vP.y;
    float sc = vC.x + vC.y;
#pragma unroll
    for (int off = 16; off; off >>= 1) {
        sp += __shfl_down_sync(0xffffffffu, sp, off);
        sc += __shfl_down_sync(0xffffffffu, sc, off);
    }
    int wid = tid >> 5, lane = tid & 31;
    if (lane == 0) { redP[wid] = sp; redC[wid] = sc; }
    __syncthreads();

    const int bid = blockIdx.y * gridDim.x + blockIdx.x;
    if (tid == 0) {
        float tp = 0.f, tc = 0.f;
#pragma unroll
        for (int i = 0; i < 8; i++) { tp += redP[i]; tc += redC[i]; }
        g_blkP[bid] = (double)tp;
        g_blkC[bid] = (double)tc;
        g_blkM[bid] = sMask;
        __threadfence();
        unsigned t = atomicInc(&g_cnt, GRID_TOTAL - 1);
        sLast = (t == GRID_TOTAL - 1);
    }
    __syncthreads();

    // ---- last block: final reduction + output ----
    if (sLast) {
        __threadfence();
        __shared__ double fP[8], fC[8];
        __shared__ float  fM[8];
        double p = g_blkP[tid];   // 256 slots, 256 threads
        double c = g_blkC[tid];
        float  m = g_blkM[tid];
#pragma unroll
        for (int off = 16; off; off >>= 1) {
            p += __shfl_down_sync(0xffffffffu, p, off);
            c += __shfl_down_sync(0xffffffffu, c, off);
            m += __shfl_down_sync(0xffffffffu, m, off);
        }
        if (lane == 0) { fP[wid] = p; fC[wid] = c; fM[wid] = m; }
        __syncthreads();
        if (tid == 0) {
            double tp = 0.0, tc = 0.0;
            float  tm = 0.f;
#pragma unroll
            for (int i = 0; i < 8; i++) { tp += fP[i]; tc += fC[i]; tm += fM[i]; }
            double denom = (tm > 1.f) ? (double)tm : 1.0;
            out[0] = (float)((tp + tc) / denom);  // final_loss
            out[1] = (float)(tp / denom);          // dist_p_m
            out[2] = (float)(tc / denom);          // dist_c_m
        }
    }
}

extern "C" void kernel_launch(void* const* d_in, const int* in_sizes, int n_in,
                              void* d_out, int out_size) {
    const float* muC  = (const float*)d_in[0];
    const float* SC   = (const float*)d_in[1];
    const float* muP  = (const float*)d_in[2];
    const float* SP   = (const float*)d_in[3];
    const float* A    = (const float*)d_in[4];
    const float* mask = (const float*)d_in[5];

    dim3 grid(GRID_X, B_);
    loss_kernel<<<grid, NTHR>>>(muC, SC, muP, SP, A, mask, (float*)d_out);
}